// round 14
// baseline (speedup 1.0000x reference)
#include <cuda_runtime.h>
#include <cuda_fp16.h>
#include <math.h>
#include <stdint.h>

#define BB 4
#define TT 1024
#define CC 1024
#define HH 16
#define HS 64
#define C3 3072
#define BHT (BB*HH)          // 64
#define NROWS (BB*HH*TT)     // 65536
#define LOG2E 1.4426950408889634f

// Scratch (device globals — no allocation allowed)
__device__ float  g_qkv[(size_t)BB*TT*C3];        // 48 MB  [B,T,3C]
__device__ __half g_probs[(size_t)BB*HH*TT*TT];   // 128 MB [B,H,T,T] e -> mod (fp16)
__device__ __half g_vht[(size_t)BHT*HS*TT];       // 8 MB   [B,H, n(hs), t] V^T fp16
__device__ __half g_kht[(size_t)BHT*TT*HS];       // 8 MB   [B,H, t, d]    K fp16
__device__ float  g_ypre[(size_t)BB*TT*CC];       // 16 MB
__device__ float  g_colsum[BHT*TT];               // 256 KB
__device__ float  g_rowinv[NROWS];                // 256 KB
__device__ float  g_effc[BHT*TT];                 // 256 KB

__device__ __forceinline__ float sigmoidf_(float x) { return 1.0f / (1.0f + expf(-x)); }
__device__ __forceinline__ float softplusf_(float x) {
    return fmaxf(x, 0.0f) + log1pf(expf(-fabsf(x)));
}
__device__ __forceinline__ uint32_t f2tf32(float x) {
    uint32_t u; asm("cvt.rna.tf32.f32 %0, %1;" : "=r"(u) : "f"(x)); return u;
}
__device__ __forceinline__ void mma_tf32(float* c, const uint32_t* a, uint32_t b0, uint32_t b1) {
    asm volatile("mma.sync.aligned.m16n8k8.row.col.f32.tf32.tf32.f32 "
        "{%0,%1,%2,%3}, {%4,%5,%6,%7}, {%8,%9}, {%0,%1,%2,%3};\n"
        : "+f"(c[0]), "+f"(c[1]), "+f"(c[2]), "+f"(c[3])
        : "r"(a[0]), "r"(a[1]), "r"(a[2]), "r"(a[3]), "r"(b0), "r"(b1));
}
__device__ __forceinline__ void mma_f16(float* c, const uint32_t* a, uint32_t b0, uint32_t b1) {
    asm volatile("mma.sync.aligned.m16n8k16.row.col.f32.f16.f16.f32 "
        "{%0,%1,%2,%3}, {%4,%5,%6,%7}, {%8,%9}, {%0,%1,%2,%3};\n"
        : "+f"(c[0]), "+f"(c[1]), "+f"(c[2]), "+f"(c[3])
        : "r"(a[0]), "r"(a[1]), "r"(a[2]), "r"(a[3]), "r"(b0), "r"(b1));
}
__device__ __forceinline__ void cp_async16(void* smem_dst, const void* gsrc) {
    uint32_t s = (uint32_t)__cvta_generic_to_shared(smem_dst);
    asm volatile("cp.async.ca.shared.global [%0], [%1], 16;\n" :: "r"(s), "l"(gsrc));
}
#define CP_COMMIT() asm volatile("cp.async.commit_group;\n" ::: "memory")
#define CP_WAIT1()  asm volatile("cp.async.wait_group 1;\n" ::: "memory")
#define CP_WAIT0()  asm volatile("cp.async.wait_group 0;\n" ::: "memory")

// ---------------------------------------------------------------------------
__global__ void init_kernel(float* refout) {
    int i = blockIdx.x * blockDim.x + threadIdx.x;
    if (i < BHT*TT) g_colsum[i] = 0.0f;
    if (i < BB*TT)  refout[i]   = 0.0f;
}

// ---------------------------------------------------------------------------
// TF32 tensor-core GEMM, cp.async double-buffered (2-stage).
// ---------------------------------------------------------------------------
#define AS_STRIDE 20
#define BS_STRIDE 136
__global__ __launch_bounds__(256, 2)
void gemm_tf32_kernel(const float* __restrict__ A,
                      const float* __restrict__ Bm,
                      const float* __restrict__ bias,
                      float* __restrict__ Co,
                      int M, int N, int K) {
    __shared__ float As[2][128 * AS_STRIDE];
    __shared__ float Bs[2][16 * BS_STRIDE];

    int tid = threadIdx.x;
    int wid = tid >> 5, lane = tid & 31;
    int g = lane >> 2, tig = lane & 3;
    int wm = wid & 1, wn = wid >> 1;
    int m_base = wm * 64, n_base = wn * 32;
    int m0 = blockIdx.y * 128, n0 = blockIdx.x * 128;

    int f0 = tid * 2, f1 = tid * 2 + 1;
    int ar0 = f0 >> 2, ak0 = (f0 & 3) * 4;
    int ar1 = f1 >> 2, ak1 = (f1 & 3) * 4;
    int bk0 = f0 >> 5, bn0 = (f0 & 31) * 4;
    int bk1 = f1 >> 5, bn1 = (f1 & 31) * 4;

    float acc[4][4][4];
    #pragma unroll
    for (int i = 0; i < 4; i++)
        #pragma unroll
        for (int j = 0; j < 4; j++)
            #pragma unroll
            for (int r = 0; r < 4; r++) acc[i][j][r] = 0.0f;

    int nt = K / 16;
    {
        cp_async16(&As[0][ar0 * AS_STRIDE + ak0], A + (size_t)(m0 + ar0) * K + ak0);
        cp_async16(&As[0][ar1 * AS_STRIDE + ak1], A + (size_t)(m0 + ar1) * K + ak1);
        cp_async16(&Bs[0][bk0 * BS_STRIDE + bn0], Bm + (size_t)bk0 * N + n0 + bn0);
        cp_async16(&Bs[0][bk1 * BS_STRIDE + bn1], Bm + (size_t)bk1 * N + n0 + bn1);
        CP_COMMIT();
    }

    for (int t = 0; t < nt; t++) {
        int cur = t & 1, nxt = cur ^ 1;
        if (t + 1 < nt) {
            int k0 = (t + 1) * 16;
            cp_async16(&As[nxt][ar0 * AS_STRIDE + ak0], A + (size_t)(m0 + ar0) * K + k0 + ak0);
            cp_async16(&As[nxt][ar1 * AS_STRIDE + ak1], A + (size_t)(m0 + ar1) * K + k0 + ak1);
            cp_async16(&Bs[nxt][bk0 * BS_STRIDE + bn0], Bm + (size_t)(k0 + bk0) * N + n0 + bn0);
            cp_async16(&Bs[nxt][bk1 * BS_STRIDE + bn1], Bm + (size_t)(k0 + bk1) * N + n0 + bn1);
            CP_COMMIT();
            CP_WAIT1();
        } else {
            CP_WAIT0();
        }
        __syncthreads();

        const float* as = As[cur];
        const float* bs = Bs[cur];
        #pragma unroll
        for (int ks = 0; ks < 16; ks += 8) {
            uint32_t af[4][4], bf[4][2];
            #pragma unroll
            for (int mf = 0; mf < 4; mf++) {
                int r0 = m_base + mf * 16 + g;
                af[mf][0] = f2tf32(as[(r0    ) * AS_STRIDE + ks + tig    ]);
                af[mf][1] = f2tf32(as[(r0 + 8) * AS_STRIDE + ks + tig    ]);
                af[mf][2] = f2tf32(as[(r0    ) * AS_STRIDE + ks + tig + 4]);
                af[mf][3] = f2tf32(as[(r0 + 8) * AS_STRIDE + ks + tig + 4]);
            }
            #pragma unroll
            for (int nf = 0; nf < 4; nf++) {
                int c0 = n_base + nf * 8 + g;
                bf[nf][0] = f2tf32(bs[(ks + tig    ) * BS_STRIDE + c0]);
                bf[nf][1] = f2tf32(bs[(ks + tig + 4) * BS_STRIDE + c0]);
            }
            #pragma unroll
            for (int mf = 0; mf < 4; mf++)
                #pragma unroll
                for (int nf = 0; nf < 4; nf++)
                    mma_tf32(acc[mf][nf], af[mf], bf[nf][0], bf[nf][1]);
        }
        __syncthreads();
    }

    #pragma unroll
    for (int mf = 0; mf < 4; mf++) {
        #pragma unroll
        for (int nf = 0; nf < 4; nf++) {
            int row = m0 + m_base + mf * 16 + g;
            int col = n0 + n_base + nf * 8 + tig * 2;
            float b0 = bias[col], b1 = bias[col + 1];
            Co[(size_t)row * N + col]           = acc[mf][nf][0] + b0;
            Co[(size_t)row * N + col + 1]       = acc[mf][nf][1] + b1;
            Co[(size_t)(row + 8) * N + col]     = acc[mf][nf][2] + b0;
            Co[(size_t)(row + 8) * N + col + 1] = acc[mf][nf][3] + b1;
        }
    }
}

// ---------------------------------------------------------------------------
// kvconvert: K slice -> g_kht fp16 [t][d]; V slice -> g_vht fp16 transposed [n][t]
// ---------------------------------------------------------------------------
__global__ __launch_bounds__(256)
void kvconvert_kernel() {
    int bh = blockIdx.x;
    int b = bh >> 4, h = bh & 15;
    int tid = threadIdx.x;

    {
        const float* src = g_qkv + (size_t)b*TT*C3 + CC + h*HS;
        __half* dst = g_kht + (size_t)bh*TT*HS;
        for (int f = tid; f < TT*8; f += 256) {
            int t = f >> 3, c8 = f & 7;
            const float* s = src + (size_t)t*C3 + c8*8;
            float4 a = *(const float4*)s;
            float4 c = *(const float4*)(s + 4);
            __half tmp[8];
            tmp[0] = __float2half_rn(a.x); tmp[1] = __float2half_rn(a.y);
            tmp[2] = __float2half_rn(a.z); tmp[3] = __float2half_rn(a.w);
            tmp[4] = __float2half_rn(c.x); tmp[5] = __float2half_rn(c.y);
            tmp[6] = __float2half_rn(c.z); tmp[7] = __float2half_rn(c.w);
            *(uint4*)(dst + (size_t)t*HS + c8*8) = *(uint4*)tmp;
        }
    }

    __shared__ __half Vt[64][65];
    const float* src = g_qkv + (size_t)b*TT*C3 + 2*CC + h*HS;
    __half* dst = g_vht + (size_t)bh*HS*TT;
    for (int t0 = 0; t0 < TT; t0 += 64) {
        #pragma unroll
        for (int s = 0; s < 4; s++) {
            int f = tid + s*256;
            int i = f >> 4, c4 = f & 15;
            float4 v = *(const float4*)(src + (size_t)(t0 + i)*C3 + c4*4);
            Vt[c4*4+0][i] = __float2half_rn(v.x);
            Vt[c4*4+1][i] = __float2half_rn(v.y);
            Vt[c4*4+2][i] = __float2half_rn(v.z);
            Vt[c4*4+3][i] = __float2half_rn(v.w);
        }
        __syncthreads();
        #pragma unroll
        for (int s = 0; s < 2; s++) {
            int f = tid + s*256;
            int n = f >> 3, c8 = f & 7;
            __half tmp[8];
            #pragma unroll
            for (int j = 0; j < 8; j++) tmp[j] = Vt[n][c8*8 + j];
            *(uint4*)(dst + (size_t)n*TT + t0 + c8*8) = *(uint4*)tmp;
        }
        __syncthreads();
    }
}

// ---------------------------------------------------------------------------
// scores + exp (fp16 store) + rowsum + fused colsum.
// 128-q strips, 256 threads. Q fragments direct from gmem (hi/lo, exact).
// K fp16 tiles streamed via cp.async. Global causal compare.
// ---------------------------------------------------------------------------
__global__ __launch_bounds__(256, 2)
void scores_exp_kernel() {
    int qtp = (int)gridDim.x - 1 - (int)blockIdx.x;   // heavy strips first, 0..7
    int bh = blockIdx.y;
    int b = bh >> 4, h = bh & 15;
    __shared__ __half RawK[2][64][72];
    __shared__ float  sinv[128];
    int tid = threadIdx.x;
    int w = tid >> 5, lane = tid & 31;
    int g = lane >> 2, tig = lane & 3;
    const float SC = 0.125f * LOG2E;
    const __half* ksrc = g_kht + (size_t)bh*TT*HS;
    int nkt = 2*qtp + 2;

    // prefetch K tile 0 (512 chunks, 2 per thread)
    {
        #pragma unroll
        for (int s = 0; s < 2; s++) {
            int ff = tid + s*256;
            int row = ff >> 3, c8 = ff & 7;
            cp_async16(&RawK[0][row][c8*8], ksrc + (size_t)row*HS + c8*8);
        }
        CP_COMMIT();
    }

    // Q fragments direct from gmem (fp16 hi/lo packed pairs), 4 k16-steps
    uint32_t qh[4][4], ql[4][4];
    {
        const float* qsrc = g_qkv + (size_t)(b*TT + qtp*128)*C3 + h*HS;
        #pragma unroll
        for (int ks = 0; ks < 4; ks++) {
            #pragma unroll
            for (int i = 0; i < 4; i++) {
                int r = w*16 + g + (i & 1)*8;
                int c = ks*16 + tig*2 + (i >> 1)*8;
                float2 v = *(const float2*)(qsrc + (size_t)r*C3 + c);
                __half h0 = __float2half_rn(v.x), h1 = __float2half_rn(v.y);
                __half l0 = __float2half_rn(v.x - __half2float(h0));
                __half l1 = __float2half_rn(v.y - __half2float(h1));
                __half hh[2] = {h0, h1}, ll[2] = {l0, l1};
                qh[ks][i] = *(uint32_t*)hh;
                ql[ks][i] = *(uint32_t*)ll;
            }
        }
    }

    float rs0 = 0.f, rs1 = 0.f;
    int lrow0 = w*16 + g;
    int qg0 = qtp*128 + lrow0;      // global q row of frag row 0 (row 1 = qg0+8)

    for (int kt = 0; kt < nkt; kt++) {
        int cur = kt & 1;
        CP_WAIT0();
        __syncthreads();
        if (kt + 1 < nkt) {
            const __half* src = ksrc + (size_t)(kt + 1)*64*HS;
            #pragma unroll
            for (int s = 0; s < 2; s++) {
                int ff = tid + s*256;
                int row = ff >> 3, c8 = ff & 7;
                cp_async16(&RawK[cur ^ 1][row][c8*8], src + (size_t)row*HS + c8*8);
            }
            CP_COMMIT();
        }

        #pragma unroll
        for (int nf = 0; nf < 8; nf++) {
            float acc[4] = {0.f, 0.f, 0.f, 0.f};
            int n = nf*8 + g;
            #pragma unroll
            for (int ks = 0; ks < 4; ks++) {
                uint32_t b0 = *(const uint32_t*)&RawK[cur][n][ks*16 + tig*2];
                uint32_t b1 = *(const uint32_t*)&RawK[cur][n][ks*16 + 8 + tig*2];
                mma_f16(acc, qh[ks], b0, b1);
                mma_f16(acc, ql[ks], b0, b1);
            }
            int kg = kt*64 + nf*8 + tig*2;
            float e00 = exp2f(acc[0]*SC);
            float e01 = exp2f(acc[1]*SC);
            float e10 = exp2f(acc[2]*SC);
            float e11 = exp2f(acc[3]*SC);
            if (kg     > qg0    ) e00 = 0.f;
            if (kg + 1 > qg0    ) e01 = 0.f;
            if (kg     > qg0 + 8) e10 = 0.f;
            if (kg + 1 > qg0 + 8) e11 = 0.f;
            rs0 += e00 + e01; rs1 += e10 + e11;
            size_t base = ((size_t)bh*TT + qg0)*TT + kg;
            *(__half2*)&g_probs[base]        = __floats2half2_rn(e00, e01);
            *(__half2*)&g_probs[base + 8*TT] = __floats2half2_rn(e10, e11);
        }
    }

    #pragma unroll
    for (int o = 1; o < 4; o <<= 1) {
        rs0 += __shfl_xor_sync(0xffffffffu, rs0, o);
        rs1 += __shfl_xor_sync(0xffffffffu, rs1, o);
    }
    if (tig == 0) {
        int r = bh*TT + qg0;
        float i0 = 1.0f / rs0, i1 = 1.0f / rs1;
        g_rowinv[r]     = i0;
        g_rowinv[r + 8] = i1;
        sinv[lrow0]     = i0;
        sinv[lrow0 + 8] = i1;
    }
    __syncthreads();

    // fused colsum over this 128-row strip (reads mostly hit L2)
    int nk = nkt * 64;
    const __half* strip = g_probs + ((size_t)bh*TT + qtp*128)*TT;
    for (int k = tid; k < nk; k += 256) {
        float s0 = 0.f, s1 = 0.f, s2 = 0.f, s3 = 0.f;
        #pragma unroll 4
        for (int i = 0; i < 128; i += 4) {
            s0 += __half2float(strip[(size_t)(i    ) * TT + k]) * sinv[i    ];
            s1 += __half2float(strip[(size_t)(i + 1) * TT + k]) * sinv[i + 1];
            s2 += __half2float(strip[(size_t)(i + 2) * TT + k]) * sinv[i + 2];
            s3 += __half2float(strip[(size_t)(i + 3) * TT + k]) * sinv[i + 3];
        }
        atomicAdd(&g_colsum[bh*TT + k], (s0 + s1) + (s2 + s3));
    }
}

// ---------------------------------------------------------------------------
// eff precompute
// ---------------------------------------------------------------------------
__global__ __launch_bounds__(256)
void eff_kernel(const float* __restrict__ refst,
                const float* __restrict__ threshold,
                const float* __restrict__ steepness,
                const float* __restrict__ ref_strength,
                const float* __restrict__ cross_w) {
    int bh = blockIdx.y;
    int b = bh >> 4, h = bh & 15;
    float thr = fabsf(threshold[h]) * 0.1f;
    float st  = softplusf_(steepness[h]);
    float rsp = softplusf_(ref_strength[h]) * (1.0f/1024.0f);
    float cw  = sigmoidf_(cross_w[h]);
    float stl2 = st * LOG2E;
    int k = blockIdx.x * 256 + threadIdx.x;
    float c = g_colsum[bh*TT + k];
    float f = refst[b*TT + k];
    g_effc[bh*TT + k] = stl2 * (thr + rsp * c + cw * f);
}

// ---------------------------------------------------------------------------
// lif modulate + renormalize (fp16 probs in/out, normalization folded)
// ---------------------------------------------------------------------------
__global__ __launch_bounds__(128)
void lifmod_kernel(const float* __restrict__ leak,
                   const float* __restrict__ steepness) {
    int r = blockIdx.x;
    int bh = r >> 10;
    int q = r & (TT - 1);
    int nk = ((q >> 6) + 1) * 64;
    int h = bh & 15;
    int tid = threadIdx.x;
    int wid = tid >> 5, lane = tid & 31;
    float lk  = sigmoidf_(leak[h]);
    float dl  = 1.0f - lk;
    float st  = softplusf_(steepness[h]);
    float rinv = g_rowinv[r];
    float nstl2r = -st * LOG2E * rinv;
    size_t base = (size_t)r * TT;
    const float* effc = g_effc + bh*TT;
    float mv[8];
    float sum = 0.0f;
    #pragma unroll
    for (int i = 0; i < 2; i++) {
        int k = i * 512 + tid * 4;
        if (k < nk) {
            __half2 h01 = *(const __half2*)&g_probs[base + k];
            __half2 h23 = *(const __half2*)&g_probs[base + k + 2];
            float2 f01 = __half22float2(h01);
            float2 f23 = __half22float2(h23);
            float4 c4 = *(const float4*)&effc[k];
            float pp[4] = {f01.x, f01.y, f23.x, f23.y};
            float cc[4] = {c4.x, c4.y, c4.z, c4.w};
            #pragma unroll
            for (int j = 0; j < 4; j++) {
                float z = fmaf(nstl2r, pp[j], cc[j]);
                float fire = __frcp_rn(1.0f + exp2f(z));
                float m = pp[j] * fmaf(dl, fire, lk);
                mv[i*4 + j] = m;
                sum += m;
            }
        } else {
            mv[i*4] = mv[i*4+1] = mv[i*4+2] = mv[i*4+3] = 0.0f;
        }
    }
    #pragma unroll
    for (int o = 16; o > 0; o >>= 1) sum += __shfl_xor_sync(0xffffffffu, sum, o);
    __shared__ float red[4];
    if (lane == 0) red[wid] = sum;
    __syncthreads();
    float tot = red[0] + red[1] + red[2] + red[3];
    float scale = rinv / (fmaf(rinv, tot, 1e-8f));
    #pragma unroll
    for (int i = 0; i < 2; i++) {
        int k = i * 512 + tid * 4;
        if (k < nk) {
            *(__half2*)&g_probs[base + k]     = __floats2half2_rn(mv[i*4]*scale,   mv[i*4+1]*scale);
            *(__half2*)&g_probs[base + k + 2] = __floats2half2_rn(mv[i*4+2]*scale, mv[i*4+3]*scale);
        }
    }
}

// ---------------------------------------------------------------------------
// y_pre = mod @ V. fp16 HMMA m16n8k16, M fp16 + VT fp16 tiles via cp.async.
// Fused refractory column reduce.
// ---------------------------------------------------------------------------
__global__ __launch_bounds__(128, 3)
void modv_kernel(float* __restrict__ refout) {
    int qt = (int)gridDim.x - 1 - (int)blockIdx.x;
    int bh = blockIdx.y;
    int b = bh >> 4;
    __shared__ __half RawM[2][64][72];
    __shared__ __half RawVT[2][64][72];   // [n][k]
    int tid = threadIdx.x;
    int w = tid >> 5, lane = tid & 31;
    int g = lane >> 2, tig = lane & 3;

    const __half* msrc_base = g_probs + ((size_t)bh*TT + qt*64)*TT;
    const __half* vtsrc     = g_vht + (size_t)bh*HS*TT;   // [n][t]

    float acc[8][4];
    #pragma unroll
    for (int nf = 0; nf < 8; nf++)
        #pragma unroll
        for (int i = 0; i < 4; i++) acc[nf][i] = 0.0f;

    {
        #pragma unroll
        for (int s = 0; s < 4; s++) {
            int ff = tid + s*128;
            int row = ff >> 3, c8 = ff & 7;
            cp_async16(&RawM[0][row][c8*8],  msrc_base + (size_t)row*TT + c8*8);
            cp_async16(&RawVT[0][row][c8*8], vtsrc + (size_t)row*TT + c8*8);
        }
        CP_COMMIT();
    }

    for (int kt = 0; kt <= qt; kt++) {
        int cur = kt & 1;
        CP_WAIT0();
        __syncthreads();
        if (kt < qt) {
            const __half* ms = msrc_base + (kt + 1)*64;
            const __half* vs = vtsrc + (kt + 1)*64;
            #pragma unroll
            for (int s = 0; s < 4; s++) {
                int ff = tid + s*128;
                int row = ff >> 3, c8 = ff & 7;
                cp_async16(&RawM[cur ^ 1][row][c8*8],  ms + (size_t)row*TT + c8*8);
                cp_async16(&RawVT[cur ^ 1][row][c8*8], vs + (size_t)row*TT + c8*8);
            }
            CP_COMMIT();
        }

        if (tid < 64) {
            float s = 0.0f;
            #pragma unroll 8
            for (int i = 0; i < 64; i++) s += __half2float(RawM[cur][i][tid]);
            atomicAdd(&refout[b*TT + kt*64 + tid], s * (1.0f / 16384.0f));
        }

        #pragma unroll
        for (int ks = 0; ks < 4; ks++) {
            uint32_t ah[4];
            int r0 = w*16 + g;
            int c0 = ks*16 + tig*2;
            ah[0] = *(const uint32_t*)&RawM[cur][r0    ][c0    ];
            ah[1] = *(const uint32_t*)&RawM[cur][r0 + 8][c0    ];
            ah[2] = *(const uint32_t*)&RawM[cur][r0    ][c0 + 8];
            ah[3] = *(const uint32_t*)&RawM[cur][r0 + 8][c0 + 8];
            #pragma unroll
            for (int nf = 0; nf < 8; nf++) {
                int n = nf*8 + g;
                uint32_t b0 = *(const uint32_t*)&RawVT[cur][n][c0    ];
                uint32_t b1 = *(const uint32_t*)&RawVT[cur][n][c0 + 8];
                mma_f16(acc[nf], ah, b0, b1);
            }
        }
    }

    #pragma unroll
    for (int nf = 0; nf < 8; nf++) {
        int row = qt*64 + w*16 + g;
        int col = nf*8 + tig*2;
        int h = bh & 15;
        float* dst = g_ypre + (size_t)(b*TT + row)*CC + h*HS + col;
        *(float2*)dst            = make_float2(acc[nf][0], acc[nf][1]);
        *(float2*)(dst + 8*CC)   = make_float2(acc[nf][2], acc[nf][3]);
    }
}

// ---------------------------------------------------------------------------
extern "C" void kernel_launch(void* const* d_in, const int* in_sizes, int n_in,
                              void* d_out, int out_size) {
    const float* x      = (const float*)d_in[0];
    const float* refst  = (const float*)d_in[1];
    const float* W_attn = (const float*)d_in[2];
    const float* b_attn = (const float*)d_in[3];
    const float* W_proj = (const float*)d_in[4];
    const float* b_proj = (const float*)d_in[5];
    const float* thr    = (const float*)d_in[6];
    const float* leak   = (const float*)d_in[7];
    const float* steep  = (const float*)d_in[8];
    const float* refstr = (const float*)d_in[9];
    const float* crossw = (const float*)d_in[10];

    float* y_out   = (float*)d_out;
    float* ref_out = (float*)d_out + (size_t)BB*TT*CC;

    float* qkv  = nullptr;  cudaGetSymbolAddress((void**)&qkv,  g_qkv);
    float* ypre = nullptr;  cudaGetSymbolAddress((void**)&ypre, g_ypre);

    init_kernel<<<(BHT*TT + 255)/256, 256>>>(ref_out);
    gemm_tf32_kernel<<<dim3(C3/128, (BB*TT)/128), 256>>>(x, W_attn, b_attn, qkv, BB*TT, C3, CC);
    kvconvert_kernel<<<BHT, 256>>>();
    scores_exp_kernel<<<dim3(TT/128, BHT), 256>>>();
    eff_kernel<<<dim3(TT/256, BHT), 256>>>(refst, thr, steep, refstr, crossw);
    lifmod_kernel<<<NROWS, 128>>>(leak, steep);
    modv_kernel<<<dim3(TT/64, BHT), 128>>>(ref_out);
    gemm_tf32_kernel<<<dim3(CC/128, (BB*TT)/128), 256>>>(ypre, W_proj, b_proj, y_out, BB*TT, CC, CC);
}

// round 15
// speedup vs baseline: 1.3427x; 1.3427x over previous
#include <cuda_runtime.h>
#include <cuda_fp16.h>
#include <math.h>
#include <stdint.h>

#define BB 4
#define TT 1024
#define CC 1024
#define HH 16
#define HS 64
#define C3 3072
#define BHT (BB*HH)          // 64
#define NROWS (BB*HH*TT)     // 65536
#define LOG2E 1.4426950408889634f

// Scratch (device globals — no allocation allowed)
__device__ float  g_qkv[(size_t)BB*TT*C3];        // 48 MB  [B,T,3C] fp32 (QKV GEMM out)
__device__ __half g_probs[(size_t)BB*HH*TT*TT];   // 128 MB [B,H,T,T] e -> mod (fp16)
__device__ __half g_vht[(size_t)BHT*HS*TT];       // 8 MB   V^T fp16 [bh][n][t]
__device__ __half g_kht[(size_t)BHT*TT*HS];       // 8 MB   K fp16 [bh][t][d]
__device__ __half g_xh[(size_t)BB*TT*CC];         // 8 MB   x fp16 [M][K]
__device__ __half g_wat[(size_t)CC*C3];           // 6 MB   W_attn^T fp16 [N][K]
__device__ __half g_wpt[(size_t)CC*CC];           // 2 MB   W_proj^T fp16 [N][K]
__device__ __half g_ypreh[(size_t)BB*TT*CC];      // 8 MB   ypre fp16 [M][K]
__device__ float  g_colsum[BHT*TT];               // 256 KB
__device__ float  g_rowinv[NROWS];                // 256 KB
__device__ float  g_effc[BHT*TT];                 // 256 KB

__device__ __forceinline__ float sigmoidf_(float x) { return 1.0f / (1.0f + expf(-x)); }
__device__ __forceinline__ float softplusf_(float x) {
    return fmaxf(x, 0.0f) + log1pf(expf(-fabsf(x)));
}
__device__ __forceinline__ void mma_f16(float* c, const uint32_t* a, uint32_t b0, uint32_t b1) {
    asm volatile("mma.sync.aligned.m16n8k16.row.col.f32.f16.f16.f32 "
        "{%0,%1,%2,%3}, {%4,%5,%6,%7}, {%8,%9}, {%0,%1,%2,%3};\n"
        : "+f"(c[0]), "+f"(c[1]), "+f"(c[2]), "+f"(c[3])
        : "r"(a[0]), "r"(a[1]), "r"(a[2]), "r"(a[3]), "r"(b0), "r"(b1));
}
__device__ __forceinline__ void cp_async16(void* smem_dst, const void* gsrc) {
    uint32_t s = (uint32_t)__cvta_generic_to_shared(smem_dst);
    asm volatile("cp.async.ca.shared.global [%0], [%1], 16;\n" :: "r"(s), "l"(gsrc));
}
#define CP_COMMIT() asm volatile("cp.async.commit_group;\n" ::: "memory")
#define CP_WAIT1()  asm volatile("cp.async.wait_group 1;\n" ::: "memory")
#define CP_WAIT0()  asm volatile("cp.async.wait_group 0;\n" ::: "memory")

// ---------------------------------------------------------------------------
__global__ void init_kernel(float* refout) {
    int i = blockIdx.x * blockDim.x + threadIdx.x;
    if (i < BHT*TT) g_colsum[i] = 0.0f;
    if (i < BB*TT)  refout[i]   = 0.0f;
}

// ---------------------------------------------------------------------------
// xconvert: x fp32 -> g_xh fp16 (straight)
// ---------------------------------------------------------------------------
__global__ __launch_bounds__(256)
void xconvert_kernel(const float* __restrict__ x) {
    size_t i = ((size_t)blockIdx.x * 256 + threadIdx.x) * 8;
    float4 a = *(const float4*)(x + i);
    float4 c = *(const float4*)(x + i + 4);
    __half tmp[8];
    tmp[0] = __float2half_rn(a.x); tmp[1] = __float2half_rn(a.y);
    tmp[2] = __float2half_rn(a.z); tmp[3] = __float2half_rn(a.w);
    tmp[4] = __float2half_rn(c.x); tmp[5] = __float2half_rn(c.y);
    tmp[6] = __float2half_rn(c.z); tmp[7] = __float2half_rn(c.w);
    *(uint4*)(g_xh + i) = *(uint4*)tmp;
}

// ---------------------------------------------------------------------------
// wtrans: W[K=1024][N] fp32 -> Wt[N][K] fp16 (64x64 tiles)
// ---------------------------------------------------------------------------
__global__ __launch_bounds__(256)
void wtrans_kernel(const float* __restrict__ W, __half* __restrict__ Wt, int N) {
    __shared__ __half Ws[64][72];   // [n_local][k_local]
    int n0 = blockIdx.x * 64, k0 = blockIdx.y * 64;
    int tid = threadIdx.x;
    #pragma unroll
    for (int s = 0; s < 4; s++) {
        int f = tid + s * 256;             // 1024 float4 chunks
        int kk = f >> 4, c4 = f & 15;
        float4 v = *(const float4*)(W + (size_t)(k0 + kk) * N + n0 + c4 * 4);
        Ws[c4*4+0][kk] = __float2half_rn(v.x);
        Ws[c4*4+1][kk] = __float2half_rn(v.y);
        Ws[c4*4+2][kk] = __float2half_rn(v.z);
        Ws[c4*4+3][kk] = __float2half_rn(v.w);
    }
    __syncthreads();
    #pragma unroll
    for (int s = 0; s < 2; s++) {
        int f = tid + s * 256;             // 512 chunks of 8 halves
        int n = f >> 3, c8 = f & 7;
        __half tmp[8];
        #pragma unroll
        for (int j = 0; j < 8; j++) tmp[j] = Ws[n][c8*8 + j];
        *(uint4*)(Wt + (size_t)(n0 + n) * CC + k0 + c8*8) = *(uint4*)tmp;
    }
}

// ---------------------------------------------------------------------------
// fp16 HMMA GEMM: Co[M,N] = A[M,K](fp16) @ Bt[N,K](fp16)^T + bias[N]
// 128x128 tile, BK=32, 2-stage cp.async, 8 warps (64x32 warp tile).
// ---------------------------------------------------------------------------
__global__ __launch_bounds__(256, 2)
void gemm_f16_kernel(const __half* __restrict__ A,
                     const __half* __restrict__ Bt,
                     const float* __restrict__ bias,
                     float* __restrict__ Co,
                     int M, int N, int K) {
    __shared__ __half As[2][128][40];
    __shared__ __half Bs[2][128][40];

    int tid = threadIdx.x;
    int wid = tid >> 5, lane = tid & 31;
    int g = lane >> 2, tig = lane & 3;
    int wm = wid & 1, wn = wid >> 1;
    int m_base = wm * 64, n_base = wn * 32;
    int m0 = blockIdx.y * 128, n0 = blockIdx.x * 128;

    int f0 = tid * 2, f1 = tid * 2 + 1;
    int r0l = f0 >> 2, c0l = (f0 & 3) * 8;
    int r1l = f1 >> 2, c1l = (f1 & 3) * 8;

    float acc[4][4][4];
    #pragma unroll
    for (int i = 0; i < 4; i++)
        #pragma unroll
        for (int j = 0; j < 4; j++)
            #pragma unroll
            for (int r = 0; r < 4; r++) acc[i][j][r] = 0.0f;

    int nt = K / 32;
    {
        cp_async16(&As[0][r0l][c0l], A + (size_t)(m0 + r0l) * K + c0l);
        cp_async16(&As[0][r1l][c1l], A + (size_t)(m0 + r1l) * K + c1l);
        cp_async16(&Bs[0][r0l][c0l], Bt + (size_t)(n0 + r0l) * K + c0l);
        cp_async16(&Bs[0][r1l][c1l], Bt + (size_t)(n0 + r1l) * K + c1l);
        CP_COMMIT();
    }

    for (int t = 0; t < nt; t++) {
        int cur = t & 1, nxt = cur ^ 1;
        if (t + 1 < nt) {
            int k0 = (t + 1) * 32;
            cp_async16(&As[nxt][r0l][c0l], A + (size_t)(m0 + r0l) * K + k0 + c0l);
            cp_async16(&As[nxt][r1l][c1l], A + (size_t)(m0 + r1l) * K + k0 + c1l);
            cp_async16(&Bs[nxt][r0l][c0l], Bt + (size_t)(n0 + r0l) * K + k0 + c0l);
            cp_async16(&Bs[nxt][r1l][c1l], Bt + (size_t)(n0 + r1l) * K + k0 + c1l);
            CP_COMMIT();
            CP_WAIT1();
        } else {
            CP_WAIT0();
        }
        __syncthreads();

        #pragma unroll
        for (int ks = 0; ks < 32; ks += 16) {
            uint32_t af[4][4], bf[4][2];
            #pragma unroll
            for (int mf = 0; mf < 4; mf++) {
                int r = m_base + mf * 16 + g;
                af[mf][0] = *(const uint32_t*)&As[cur][r    ][ks + tig*2    ];
                af[mf][1] = *(const uint32_t*)&As[cur][r + 8][ks + tig*2    ];
                af[mf][2] = *(const uint32_t*)&As[cur][r    ][ks + tig*2 + 8];
                af[mf][3] = *(const uint32_t*)&As[cur][r + 8][ks + tig*2 + 8];
            }
            #pragma unroll
            for (int nf = 0; nf < 4; nf++) {
                int n = n_base + nf * 8 + g;
                bf[nf][0] = *(const uint32_t*)&Bs[cur][n][ks + tig*2    ];
                bf[nf][1] = *(const uint32_t*)&Bs[cur][n][ks + tig*2 + 8];
            }
            #pragma unroll
            for (int mf = 0; mf < 4; mf++)
                #pragma unroll
                for (int nf = 0; nf < 4; nf++)
                    mma_f16(acc[mf][nf], af[mf], bf[nf][0], bf[nf][1]);
        }
        __syncthreads();
    }

    #pragma unroll
    for (int mf = 0; mf < 4; mf++) {
        #pragma unroll
        for (int nf = 0; nf < 4; nf++) {
            int row = m0 + m_base + mf * 16 + g;
            int col = n0 + n_base + nf * 8 + tig * 2;
            float b0 = bias[col], b1 = bias[col + 1];
            Co[(size_t)row * N + col]           = acc[mf][nf][0] + b0;
            Co[(size_t)row * N + col + 1]       = acc[mf][nf][1] + b1;
            Co[(size_t)(row + 8) * N + col]     = acc[mf][nf][2] + b0;
            Co[(size_t)(row + 8) * N + col + 1] = acc[mf][nf][3] + b1;
        }
    }
}

// ---------------------------------------------------------------------------
// kvconvert: K slice -> g_kht fp16 [t][d]; V slice -> g_vht fp16 transposed [n][t]
// ---------------------------------------------------------------------------
__global__ __launch_bounds__(256)
void kvconvert_kernel() {
    int bh = blockIdx.x;
    int b = bh >> 4, h = bh & 15;
    int tid = threadIdx.x;

    {
        const float* src = g_qkv + (size_t)b*TT*C3 + CC + h*HS;
        __half* dst = g_kht + (size_t)bh*TT*HS;
        for (int f = tid; f < TT*8; f += 256) {
            int t = f >> 3, c8 = f & 7;
            const float* s = src + (size_t)t*C3 + c8*8;
            float4 a = *(const float4*)s;
            float4 c = *(const float4*)(s + 4);
            __half tmp[8];
            tmp[0] = __float2half_rn(a.x); tmp[1] = __float2half_rn(a.y);
            tmp[2] = __float2half_rn(a.z); tmp[3] = __float2half_rn(a.w);
            tmp[4] = __float2half_rn(c.x); tmp[5] = __float2half_rn(c.y);
            tmp[6] = __float2half_rn(c.z); tmp[7] = __float2half_rn(c.w);
            *(uint4*)(dst + (size_t)t*HS + c8*8) = *(uint4*)tmp;
        }
    }

    __shared__ __half Vt[64][65];
    const float* src = g_qkv + (size_t)b*TT*C3 + 2*CC + h*HS;
    __half* dst = g_vht + (size_t)bh*HS*TT;
    for (int t0 = 0; t0 < TT; t0 += 64) {
        #pragma unroll
        for (int s = 0; s < 4; s++) {
            int f = tid + s*256;
            int i = f >> 4, c4 = f & 15;
            float4 v = *(const float4*)(src + (size_t)(t0 + i)*C3 + c4*4);
            Vt[c4*4+0][i] = __float2half_rn(v.x);
            Vt[c4*4+1][i] = __float2half_rn(v.y);
            Vt[c4*4+2][i] = __float2half_rn(v.z);
            Vt[c4*4+3][i] = __float2half_rn(v.w);
        }
        __syncthreads();
        #pragma unroll
        for (int s = 0; s < 2; s++) {
            int f = tid + s*256;
            int n = f >> 3, c8 = f & 7;
            __half tmp[8];
            #pragma unroll
            for (int j = 0; j < 8; j++) tmp[j] = Vt[n][c8*8 + j];
            *(uint4*)(dst + (size_t)n*TT + t0 + c8*8) = *(uint4*)tmp;
        }
        __syncthreads();
    }
}

// ---------------------------------------------------------------------------
// scores + exp (fp16 store) + rowsum + fused colsum. (round-13 proven version)
// ---------------------------------------------------------------------------
__global__ __launch_bounds__(128, 4)
void scores_exp_kernel() {
    int qt = (int)gridDim.x - 1 - (int)blockIdx.x;   // heavy blocks first
    int bh = blockIdx.y;
    int b = bh >> 4, h = bh & 15;
    __shared__ float  Qs[64][68];
    __shared__ __half RawK[2][64][72];
    __shared__ float  sinv[64];
    int tid = threadIdx.x;
    int w = tid >> 5, lane = tid & 31;
    int g = lane >> 2, tig = lane & 3;
    const float SC = 0.125f * LOG2E;
    const __half* ksrc = g_kht + (size_t)bh*TT*HS;

    {
        #pragma unroll
        for (int s = 0; s < 4; s++) {
            int ff = tid + s*128;
            int row = ff >> 3, c8 = ff & 7;
            cp_async16(&RawK[0][row][c8*8], ksrc + (size_t)row*HS + c8*8);
        }
        CP_COMMIT();
    }

    {
        const float* src = g_qkv + (size_t)(b*TT + qt*64)*C3 + h*HS;
        #pragma unroll
        for (int s = 0; s < 8; s++) {
            int f = tid + s*128;
            int row = f >> 4, c4 = f & 15;
            float4 v = *(const float4*)(src + (size_t)row*C3 + c4*4);
            *(float4*)&Qs[row][c4*4] = v;
        }
    }
    __syncthreads();

    uint32_t qh[4][4], ql[4][4];
    #pragma unroll
    for (int ks = 0; ks < 4; ks++) {
        #pragma unroll
        for (int i = 0; i < 4; i++) {
            int r = w*16 + g + (i & 1)*8;
            int c = ks*16 + tig*2 + (i >> 1)*8;
            float v0 = Qs[r][c], v1 = Qs[r][c + 1];
            __half h0 = __float2half_rn(v0), h1 = __float2half_rn(v1);
            __half l0 = __float2half_rn(v0 - __half2float(h0));
            __half l1 = __float2half_rn(v1 - __half2float(h1));
            __half hh[2] = {h0, h1}, ll[2] = {l0, l1};
            qh[ks][i] = *(uint32_t*)hh;
            ql[ks][i] = *(uint32_t*)ll;
        }
    }

    float rs0 = 0.f, rs1 = 0.f;
    int lrow0 = w*16 + g, lrow1 = lrow0 + 8;

    for (int kt = 0; kt <= qt; kt++) {
        int cur = kt & 1;
        CP_WAIT0();
        __syncthreads();
        if (kt < qt) {
            const __half* src = ksrc + (size_t)(kt + 1)*64*HS;
            #pragma unroll
            for (int s = 0; s < 4; s++) {
                int ff = tid + s*128;
                int row = ff >> 3, c8 = ff & 7;
                cp_async16(&RawK[cur ^ 1][row][c8*8], src + (size_t)row*HS + c8*8);
            }
            CP_COMMIT();
        }

        #pragma unroll
        for (int nf = 0; nf < 8; nf++) {
            float acc[4] = {0.f, 0.f, 0.f, 0.f};
            int n = nf*8 + g;
            #pragma unroll
            for (int ks = 0; ks < 4; ks++) {
                uint32_t b0 = *(const uint32_t*)&RawK[cur][n][ks*16 + tig*2];
                uint32_t b1 = *(const uint32_t*)&RawK[cur][n][ks*16 + 8 + tig*2];
                mma_f16(acc, qh[ks], b0, b1);
                mma_f16(acc, ql[ks], b0, b1);
            }
            int lcol = nf*8 + tig*2;
            float e00 = exp2f(acc[0]*SC);
            float e01 = exp2f(acc[1]*SC);
            float e10 = exp2f(acc[2]*SC);
            float e11 = exp2f(acc[3]*SC);
            if (kt == qt) {
                if (lcol     > lrow0) e00 = 0.f;
                if (lcol + 1 > lrow0) e01 = 0.f;
                if (lcol     > lrow1) e10 = 0.f;
                if (lcol + 1 > lrow1) e11 = 0.f;
            }
            rs0 += e00 + e01; rs1 += e10 + e11;
            size_t base = ((size_t)bh*TT + qt*64 + lrow0)*TT + kt*64 + lcol;
            *(__half2*)&g_probs[base]        = __floats2half2_rn(e00, e01);
            *(__half2*)&g_probs[base + 8*TT] = __floats2half2_rn(e10, e11);
        }
    }

    #pragma unroll
    for (int o = 1; o < 4; o <<= 1) {
        rs0 += __shfl_xor_sync(0xffffffffu, rs0, o);
        rs1 += __shfl_xor_sync(0xffffffffu, rs1, o);
    }
    if (tig == 0) {
        int r = bh*TT + qt*64 + lrow0;
        float i0 = 1.0f / rs0, i1 = 1.0f / rs1;
        g_rowinv[r]     = i0;
        g_rowinv[r + 8] = i1;
        sinv[lrow0]     = i0;
        sinv[lrow1]     = i1;
    }
    __syncthreads();

    int nk = (qt + 1) * 64;
    const __half* strip = g_probs + ((size_t)bh*TT + qt*64)*TT;
    for (int k = tid; k < nk; k += 128) {
        float s0 = 0.f, s1 = 0.f, s2 = 0.f, s3 = 0.f;
        #pragma unroll
        for (int i = 0; i < 64; i += 4) {
            s0 += __half2float(strip[(size_t)(i    ) * TT + k]) * sinv[i    ];
            s1 += __half2float(strip[(size_t)(i + 1) * TT + k]) * sinv[i + 1];
            s2 += __half2float(strip[(size_t)(i + 2) * TT + k]) * sinv[i + 2];
            s3 += __half2float(strip[(size_t)(i + 3) * TT + k]) * sinv[i + 3];
        }
        atomicAdd(&g_colsum[bh*TT + k], (s0 + s1) + (s2 + s3));
    }
}

// ---------------------------------------------------------------------------
// eff precompute
// ---------------------------------------------------------------------------
__global__ __launch_bounds__(256)
void eff_kernel(const float* __restrict__ refst,
                const float* __restrict__ threshold,
                const float* __restrict__ steepness,
                const float* __restrict__ ref_strength,
                const float* __restrict__ cross_w) {
    int bh = blockIdx.y;
    int b = bh >> 4, h = bh & 15;
    float thr = fabsf(threshold[h]) * 0.1f;
    float st  = softplusf_(steepness[h]);
    float rsp = softplusf_(ref_strength[h]) * (1.0f/1024.0f);
    float cw  = sigmoidf_(cross_w[h]);
    float stl2 = st * LOG2E;
    int k = blockIdx.x * 256 + threadIdx.x;
    float c = g_colsum[bh*TT + k];
    float f = refst[b*TT + k];
    g_effc[bh*TT + k] = stl2 * (thr + rsp * c + cw * f);
}

// ---------------------------------------------------------------------------
// lif modulate + renormalize (fp16 probs in/out, normalization folded)
// ---------------------------------------------------------------------------
__global__ __launch_bounds__(128)
void lifmod_kernel(const float* __restrict__ leak,
                   const float* __restrict__ steepness) {
    int r = blockIdx.x;
    int bh = r >> 10;
    int q = r & (TT - 1);
    int nk = ((q >> 6) + 1) * 64;
    int h = bh & 15;
    int tid = threadIdx.x;
    int wid = tid >> 5, lane = tid & 31;
    float lk  = sigmoidf_(leak[h]);
    float dl  = 1.0f - lk;
    float st  = softplusf_(steepness[h]);
    float rinv = g_rowinv[r];
    float nstl2r = -st * LOG2E * rinv;
    size_t base = (size_t)r * TT;
    const float* effc = g_effc + bh*TT;
    float mv[8];
    float sum = 0.0f;
    #pragma unroll
    for (int i = 0; i < 2; i++) {
        int k = i * 512 + tid * 4;
        if (k < nk) {
            __half2 h01 = *(const __half2*)&g_probs[base + k];
            __half2 h23 = *(const __half2*)&g_probs[base + k + 2];
            float2 f01 = __half22float2(h01);
            float2 f23 = __half22float2(h23);
            float4 c4 = *(const float4*)&effc[k];
            float pp[4] = {f01.x, f01.y, f23.x, f23.y};
            float cc[4] = {c4.x, c4.y, c4.z, c4.w};
            #pragma unroll
            for (int j = 0; j < 4; j++) {
                float z = fmaf(nstl2r, pp[j], cc[j]);
                float fire = __frcp_rn(1.0f + exp2f(z));
                float m = pp[j] * fmaf(dl, fire, lk);
                mv[i*4 + j] = m;
                sum += m;
            }
        } else {
            mv[i*4] = mv[i*4+1] = mv[i*4+2] = mv[i*4+3] = 0.0f;
        }
    }
    #pragma unroll
    for (int o = 16; o > 0; o >>= 1) sum += __shfl_xor_sync(0xffffffffu, sum, o);
    __shared__ float red[4];
    if (lane == 0) red[wid] = sum;
    __syncthreads();
    float tot = red[0] + red[1] + red[2] + red[3];
    float scale = rinv / (fmaf(rinv, tot, 1e-8f));
    #pragma unroll
    for (int i = 0; i < 2; i++) {
        int k = i * 512 + tid * 4;
        if (k < nk) {
            *(__half2*)&g_probs[base + k]     = __floats2half2_rn(mv[i*4]*scale,   mv[i*4+1]*scale);
            *(__half2*)&g_probs[base + k + 2] = __floats2half2_rn(mv[i*4+2]*scale, mv[i*4+3]*scale);
        }
    }
}

// ---------------------------------------------------------------------------
// y_pre = mod @ V. fp16 HMMA, fp16 ypre output. Fused refractory reduce.
// ---------------------------------------------------------------------------
__global__ __launch_bounds__(128, 3)
void modv_kernel(float* __restrict__ refout) {
    int qt = (int)gridDim.x - 1 - (int)blockIdx.x;
    int bh = blockIdx.y;
    int b = bh >> 4;
    __shared__ __half RawM[2][64][72];
    __shared__ __half RawVT[2][64][72];   // [n][k]
    int tid = threadIdx.x;
    int w = tid >> 5, lane = tid & 31;
    int g = lane >> 2, tig = lane & 3;

    const __half* msrc_base = g_probs + ((size_t)bh*TT + qt*64)*TT;
    const __half* vtsrc     = g_vht + (size_t)bh*HS*TT;

    float acc[8][4];
    #pragma unroll
    for (int nf = 0; nf < 8; nf++)
        #pragma unroll
        for (int i = 0; i < 4; i++) acc[nf][i] = 0.0f;

    {
        #pragma unroll
        for (int s = 0; s < 4; s++) {
            int ff = tid + s*128;
            int row = ff >> 3, c8 = ff & 7;
            cp_async16(&RawM[0][row][c8*8],  msrc_base + (size_t)row*TT + c8*8);
            cp_async16(&RawVT[0][row][c8*8], vtsrc + (size_t)row*TT + c8*8);
        }
        CP_COMMIT();
    }

    for (int kt = 0; kt <= qt; kt++) {
        int cur = kt & 1;
        CP_WAIT0();
        __syncthreads();
        if (kt < qt) {
            const __half* ms = msrc_base + (kt + 1)*64;
            const __half* vs = vtsrc + (kt + 1)*64;
            #pragma unroll
            for (int s = 0; s < 4; s++) {
                int ff = tid + s*128;
                int row = ff >> 3, c8 = ff & 7;
                cp_async16(&RawM[cur ^ 1][row][c8*8],  ms + (size_t)row*TT + c8*8);
                cp_async16(&RawVT[cur ^ 1][row][c8*8], vs + (size_t)row*TT + c8*8);
            }
            CP_COMMIT();
        }

        if (tid < 64) {
            float s = 0.0f;
            #pragma unroll 8
            for (int i = 0; i < 64; i++) s += __half2float(RawM[cur][i][tid]);
            atomicAdd(&refout[b*TT + kt*64 + tid], s * (1.0f / 16384.0f));
        }

        #pragma unroll
        for (int ks = 0; ks < 4; ks++) {
            uint32_t ah[4];
            int r0 = w*16 + g;
            int c0 = ks*16 + tig*2;
            ah[0] = *(const uint32_t*)&RawM[cur][r0    ][c0    ];
            ah[1] = *(const uint32_t*)&RawM[cur][r0 + 8][c0    ];
            ah[2] = *(const uint32_t*)&RawM[cur][r0    ][c0 + 8];
            ah[3] = *(const uint32_t*)&RawM[cur][r0 + 8][c0 + 8];
            #pragma unroll
            for (int nf = 0; nf < 8; nf++) {
                int n = nf*8 + g;
                uint32_t b0 = *(const uint32_t*)&RawVT[cur][n][c0    ];
                uint32_t b1 = *(const uint32_t*)&RawVT[cur][n][c0 + 8];
                mma_f16(acc[nf], ah, b0, b1);
            }
        }
    }

    #pragma unroll
    for (int nf = 0; nf < 8; nf++) {
        int row = qt*64 + w*16 + g;
        int col = nf*8 + tig*2;
        int h = bh & 15;
        __half* dst = g_ypreh + (size_t)(b*TT + row)*CC + h*HS + col;
        *(__half2*)dst          = __floats2half2_rn(acc[nf][0], acc[nf][1]);
        *(__half2*)(dst + 8*CC) = __floats2half2_rn(acc[nf][2], acc[nf][3]);
    }
}

// ---------------------------------------------------------------------------
extern "C" void kernel_launch(void* const* d_in, const int* in_sizes, int n_in,
                              void* d_out, int out_size) {
    const float* x      = (const float*)d_in[0];
    const float* refst  = (const float*)d_in[1];
    const float* W_attn = (const float*)d_in[2];
    const float* b_attn = (const float*)d_in[3];
    const float* W_proj = (const float*)d_in[4];
    const float* b_proj = (const float*)d_in[5];
    const float* thr    = (const float*)d_in[6];
    const float* leak   = (const float*)d_in[7];
    const float* steep  = (const float*)d_in[8];
    const float* refstr = (const float*)d_in[9];
    const float* crossw = (const float*)d_in[10];

    float* y_out   = (float*)d_out;
    float* ref_out = (float*)d_out + (size_t)BB*TT*CC;

    float*  qkv   = nullptr;  cudaGetSymbolAddress((void**)&qkv,   g_qkv);
    __half* xh    = nullptr;  cudaGetSymbolAddress((void**)&xh,    g_xh);
    __half* wat   = nullptr;  cudaGetSymbolAddress((void**)&wat,   g_wat);
    __half* wpt   = nullptr;  cudaGetSymbolAddress((void**)&wpt,   g_wpt);
    __half* ypreh = nullptr;  cudaGetSymbolAddress((void**)&ypreh, g_ypreh);

    init_kernel<<<(BHT*TT + 255)/256, 256>>>(ref_out);
    xconvert_kernel<<<(BB*TT*CC)/(256*8), 256>>>(x);
    wtrans_kernel<<<dim3(C3/64, CC/64), 256>>>(W_attn, wat, C3);
    wtrans_kernel<<<dim3(CC/64, CC/64), 256>>>(W_proj, wpt, CC);
    gemm_f16_kernel<<<dim3(C3/128, (BB*TT)/128), 256>>>(xh, wat, b_attn, qkv, BB*TT, C3, CC);
    kvconvert_kernel<<<BHT, 256>>>();
    scores_exp_kernel<<<dim3(TT/64, BHT), 128>>>();
    eff_kernel<<<dim3(TT/256, BHT), 256>>>(refst, thr, steep, refstr, crossw);
    lifmod_kernel<<<NROWS, 128>>>(leak, steep);
    modv_kernel<<<dim3(TT/64, BHT), 128>>>(ref_out);
    gemm_f16_kernel<<<dim3(CC/128, (BB*TT)/128), 256>>>(ypreh, wpt, b_proj, y_out, BB*TT, CC, CC);
}

// round 16
// speedup vs baseline: 1.3826x; 1.0297x over previous
#include <cuda_runtime.h>
#include <cuda_fp16.h>
#include <math.h>
#include <stdint.h>

#define BB 4
#define TT 1024
#define CC 1024
#define HH 16
#define HS 64
#define C3 3072
#define BHT (BB*HH)          // 64
#define NROWS (BB*HH*TT)     // 65536
#define LOG2E 1.4426950408889634f

// Scratch (device globals — no allocation allowed)
__device__ float  g_qkv[(size_t)BB*TT*C3];        // 48 MB  [B,T,3C] fp32 (QKV GEMM out)
__device__ __half g_probs[(size_t)BB*HH*TT*TT];   // 128 MB [B,H,T,T] e -> mod (fp16)
__device__ __half g_vht[(size_t)BHT*HS*TT];       // 8 MB   V^T fp16 [bh][n][t]
__device__ __half g_kht[(size_t)BHT*TT*HS];       // 8 MB   K fp16 [bh][t][d]
__device__ __half g_xh[(size_t)BB*TT*CC];         // 8 MB   x fp16 [M][K]
__device__ __half g_wat[(size_t)CC*C3];           // 6 MB   W_attn^T fp16 [N][K]
__device__ __half g_wpt[(size_t)CC*CC];           // 2 MB   W_proj^T fp16 [N][K]
__device__ __half g_ypreh[(size_t)BB*TT*CC];      // 8 MB   ypre fp16 [M][K]
__device__ float  g_colsum[BHT*TT];               // 256 KB
__device__ float  g_rowinv[NROWS];                // 256 KB
__device__ float  g_effc[BHT*TT];                 // 256 KB

__device__ __forceinline__ float sigmoidf_(float x) { return 1.0f / (1.0f + expf(-x)); }
__device__ __forceinline__ float softplusf_(float x) {
    return fmaxf(x, 0.0f) + log1pf(expf(-fabsf(x)));
}
__device__ __forceinline__ void mma_f16(float* c, const uint32_t* a, uint32_t b0, uint32_t b1) {
    asm volatile("mma.sync.aligned.m16n8k16.row.col.f32.f16.f16.f32 "
        "{%0,%1,%2,%3}, {%4,%5,%6,%7}, {%8,%9}, {%0,%1,%2,%3};\n"
        : "+f"(c[0]), "+f"(c[1]), "+f"(c[2]), "+f"(c[3])
        : "r"(a[0]), "r"(a[1]), "r"(a[2]), "r"(a[3]), "r"(b0), "r"(b1));
}
__device__ __forceinline__ void cp_async16(void* smem_dst, const void* gsrc) {
    uint32_t s = (uint32_t)__cvta_generic_to_shared(smem_dst);
    asm volatile("cp.async.ca.shared.global [%0], [%1], 16;\n" :: "r"(s), "l"(gsrc));
}
#define CP_COMMIT() asm volatile("cp.async.commit_group;\n" ::: "memory")
#define CP_WAIT1()  asm volatile("cp.async.wait_group 1;\n" ::: "memory")
#define CP_WAIT0()  asm volatile("cp.async.wait_group 0;\n" ::: "memory")

// ---------------------------------------------------------------------------
__global__ void init_kernel(float* refout) {
    int i = blockIdx.x * blockDim.x + threadIdx.x;
    if (i < BHT*TT) g_colsum[i] = 0.0f;
    if (i < BB*TT)  refout[i]   = 0.0f;
}

// ---------------------------------------------------------------------------
// xconvert: x fp32 -> g_xh fp16 (straight)
// ---------------------------------------------------------------------------
__global__ __launch_bounds__(256)
void xconvert_kernel(const float* __restrict__ x) {
    size_t i = ((size_t)blockIdx.x * 256 + threadIdx.x) * 8;
    float4 a = *(const float4*)(x + i);
    float4 c = *(const float4*)(x + i + 4);
    __half tmp[8];
    tmp[0] = __float2half_rn(a.x); tmp[1] = __float2half_rn(a.y);
    tmp[2] = __float2half_rn(a.z); tmp[3] = __float2half_rn(a.w);
    tmp[4] = __float2half_rn(c.x); tmp[5] = __float2half_rn(c.y);
    tmp[6] = __float2half_rn(c.z); tmp[7] = __float2half_rn(c.w);
    *(uint4*)(g_xh + i) = *(uint4*)tmp;
}

// ---------------------------------------------------------------------------
// wtrans: W[K=1024][N] fp32 -> Wt[N][K] fp16 (64x64 tiles)
// ---------------------------------------------------------------------------
__global__ __launch_bounds__(256)
void wtrans_kernel(const float* __restrict__ W, __half* __restrict__ Wt, int N) {
    __shared__ __half Ws[64][72];
    int n0 = blockIdx.x * 64, k0 = blockIdx.y * 64;
    int tid = threadIdx.x;
    #pragma unroll
    for (int s = 0; s < 4; s++) {
        int f = tid + s * 256;
        int kk = f >> 4, c4 = f & 15;
        float4 v = *(const float4*)(W + (size_t)(k0 + kk) * N + n0 + c4 * 4);
        Ws[c4*4+0][kk] = __float2half_rn(v.x);
        Ws[c4*4+1][kk] = __float2half_rn(v.y);
        Ws[c4*4+2][kk] = __float2half_rn(v.z);
        Ws[c4*4+3][kk] = __float2half_rn(v.w);
    }
    __syncthreads();
    #pragma unroll
    for (int s = 0; s < 2; s++) {
        int f = tid + s * 256;
        int n = f >> 3, c8 = f & 7;
        __half tmp[8];
        #pragma unroll
        for (int j = 0; j < 8; j++) tmp[j] = Ws[n][c8*8 + j];
        *(uint4*)(Wt + (size_t)(n0 + n) * CC + k0 + c8*8) = *(uint4*)tmp;
    }
}

// ---------------------------------------------------------------------------
// fp16 HMMA GEMM: Co[M,N] = A[M,K](fp16) @ Bt[N,K](fp16)^T + bias[N]
// ---------------------------------------------------------------------------
__global__ __launch_bounds__(256, 2)
void gemm_f16_kernel(const __half* __restrict__ A,
                     const __half* __restrict__ Bt,
                     const float* __restrict__ bias,
                     float* __restrict__ Co,
                     int M, int N, int K) {
    __shared__ __half As[2][128][40];
    __shared__ __half Bs[2][128][40];

    int tid = threadIdx.x;
    int wid = tid >> 5, lane = tid & 31;
    int g = lane >> 2, tig = lane & 3;
    int wm = wid & 1, wn = wid >> 1;
    int m_base = wm * 64, n_base = wn * 32;
    int m0 = blockIdx.y * 128, n0 = blockIdx.x * 128;

    int f0 = tid * 2, f1 = tid * 2 + 1;
    int r0l = f0 >> 2, c0l = (f0 & 3) * 8;
    int r1l = f1 >> 2, c1l = (f1 & 3) * 8;

    float acc[4][4][4];
    #pragma unroll
    for (int i = 0; i < 4; i++)
        #pragma unroll
        for (int j = 0; j < 4; j++)
            #pragma unroll
            for (int r = 0; r < 4; r++) acc[i][j][r] = 0.0f;

    int nt = K / 32;
    {
        cp_async16(&As[0][r0l][c0l], A + (size_t)(m0 + r0l) * K + c0l);
        cp_async16(&As[0][r1l][c1l], A + (size_t)(m0 + r1l) * K + c1l);
        cp_async16(&Bs[0][r0l][c0l], Bt + (size_t)(n0 + r0l) * K + c0l);
        cp_async16(&Bs[0][r1l][c1l], Bt + (size_t)(n0 + r1l) * K + c1l);
        CP_COMMIT();
    }

    for (int t = 0; t < nt; t++) {
        int cur = t & 1, nxt = cur ^ 1;
        if (t + 1 < nt) {
            int k0 = (t + 1) * 32;
            cp_async16(&As[nxt][r0l][c0l], A + (size_t)(m0 + r0l) * K + k0 + c0l);
            cp_async16(&As[nxt][r1l][c1l], A + (size_t)(m0 + r1l) * K + k0 + c1l);
            cp_async16(&Bs[nxt][r0l][c0l], Bt + (size_t)(n0 + r0l) * K + k0 + c0l);
            cp_async16(&Bs[nxt][r1l][c1l], Bt + (size_t)(n0 + r1l) * K + k0 + c1l);
            CP_COMMIT();
            CP_WAIT1();
        } else {
            CP_WAIT0();
        }
        __syncthreads();

        #pragma unroll
        for (int ks = 0; ks < 32; ks += 16) {
            uint32_t af[4][4], bf[4][2];
            #pragma unroll
            for (int mf = 0; mf < 4; mf++) {
                int r = m_base + mf * 16 + g;
                af[mf][0] = *(const uint32_t*)&As[cur][r    ][ks + tig*2    ];
                af[mf][1] = *(const uint32_t*)&As[cur][r + 8][ks + tig*2    ];
                af[mf][2] = *(const uint32_t*)&As[cur][r    ][ks + tig*2 + 8];
                af[mf][3] = *(const uint32_t*)&As[cur][r + 8][ks + tig*2 + 8];
            }
            #pragma unroll
            for (int nf = 0; nf < 4; nf++) {
                int n = n_base + nf * 8 + g;
                bf[nf][0] = *(const uint32_t*)&Bs[cur][n][ks + tig*2    ];
                bf[nf][1] = *(const uint32_t*)&Bs[cur][n][ks + tig*2 + 8];
            }
            #pragma unroll
            for (int mf = 0; mf < 4; mf++)
                #pragma unroll
                for (int nf = 0; nf < 4; nf++)
                    mma_f16(acc[mf][nf], af[mf], bf[nf][0], bf[nf][1]);
        }
        __syncthreads();
    }

    #pragma unroll
    for (int mf = 0; mf < 4; mf++) {
        #pragma unroll
        for (int nf = 0; nf < 4; nf++) {
            int row = m0 + m_base + mf * 16 + g;
            int col = n0 + n_base + nf * 8 + tig * 2;
            float b0 = bias[col], b1 = bias[col + 1];
            Co[(size_t)row * N + col]           = acc[mf][nf][0] + b0;
            Co[(size_t)row * N + col + 1]       = acc[mf][nf][1] + b1;
            Co[(size_t)(row + 8) * N + col]     = acc[mf][nf][2] + b0;
            Co[(size_t)(row + 8) * N + col + 1] = acc[mf][nf][3] + b1;
        }
    }
}

// ---------------------------------------------------------------------------
// kvconvert: K slice -> g_kht fp16 [t][d]; V slice -> g_vht fp16 transposed [n][t]
// ---------------------------------------------------------------------------
__global__ __launch_bounds__(256)
void kvconvert_kernel() {
    int bh = blockIdx.x;
    int b = bh >> 4, h = bh & 15;
    int tid = threadIdx.x;

    {
        const float* src = g_qkv + (size_t)b*TT*C3 + CC + h*HS;
        __half* dst = g_kht + (size_t)bh*TT*HS;
        for (int f = tid; f < TT*8; f += 256) {
            int t = f >> 3, c8 = f & 7;
            const float* s = src + (size_t)t*C3 + c8*8;
            float4 a = *(const float4*)s;
            float4 c = *(const float4*)(s + 4);
            __half tmp[8];
            tmp[0] = __float2half_rn(a.x); tmp[1] = __float2half_rn(a.y);
            tmp[2] = __float2half_rn(a.z); tmp[3] = __float2half_rn(a.w);
            tmp[4] = __float2half_rn(c.x); tmp[5] = __float2half_rn(c.y);
            tmp[6] = __float2half_rn(c.z); tmp[7] = __float2half_rn(c.w);
            *(uint4*)(dst + (size_t)t*HS + c8*8) = *(uint4*)tmp;
        }
    }

    __shared__ __half Vt[64][65];
    const float* src = g_qkv + (size_t)b*TT*C3 + 2*CC + h*HS;
    __half* dst = g_vht + (size_t)bh*HS*TT;
    for (int t0 = 0; t0 < TT; t0 += 64) {
        #pragma unroll
        for (int s = 0; s < 4; s++) {
            int f = tid + s*256;
            int i = f >> 4, c4 = f & 15;
            float4 v = *(const float4*)(src + (size_t)(t0 + i)*C3 + c4*4);
            Vt[c4*4+0][i] = __float2half_rn(v.x);
            Vt[c4*4+1][i] = __float2half_rn(v.y);
            Vt[c4*4+2][i] = __float2half_rn(v.z);
            Vt[c4*4+3][i] = __float2half_rn(v.w);
        }
        __syncthreads();
        #pragma unroll
        for (int s = 0; s < 2; s++) {
            int f = tid + s*256;
            int n = f >> 3, c8 = f & 7;
            __half tmp[8];
            #pragma unroll
            for (int j = 0; j < 8; j++) tmp[j] = Vt[n][c8*8 + j];
            *(uint4*)(dst + (size_t)n*TT + t0 + c8*8) = *(uint4*)tmp;
        }
        __syncthreads();
    }
}

// ---------------------------------------------------------------------------
// scores + exp (fp16 store) + rowsum + fused colsum.
// Pure fp16 HMMA (Q hi only), Q fragments direct from gmem, no Qs smem.
// ---------------------------------------------------------------------------
__global__ __launch_bounds__(128, 6)
void scores_exp_kernel() {
    int qt = (int)gridDim.x - 1 - (int)blockIdx.x;   // heavy blocks first
    int bh = blockIdx.y;
    int b = bh >> 4, h = bh & 15;
    __shared__ __half RawK[2][64][72];
    __shared__ float  sinv[64];
    int tid = threadIdx.x;
    int w = tid >> 5, lane = tid & 31;
    int g = lane >> 2, tig = lane & 3;
    const float SC = 0.125f * LOG2E;
    const __half* ksrc = g_kht + (size_t)bh*TT*HS;

    // prefetch K tile 0
    {
        #pragma unroll
        for (int s = 0; s < 4; s++) {
            int ff = tid + s*128;
            int row = ff >> 3, c8 = ff & 7;
            cp_async16(&RawK[0][row][c8*8], ksrc + (size_t)row*HS + c8*8);
        }
        CP_COMMIT();
    }

    // Q fragments direct from gmem (fp16 packed pairs), 4 k16-steps
    uint32_t qh[4][4];
    {
        const float* qsrc = g_qkv + (size_t)(b*TT + qt*64)*C3 + h*HS;
        #pragma unroll
        for (int ks = 0; ks < 4; ks++) {
            #pragma unroll
            for (int i = 0; i < 4; i++) {
                int r = w*16 + g + (i & 1)*8;
                int c = ks*16 + tig*2 + (i >> 1)*8;
                float2 v = *(const float2*)(qsrc + (size_t)r*C3 + c);
                __half hh[2] = {__float2half_rn(v.x), __float2half_rn(v.y)};
                qh[ks][i] = *(uint32_t*)hh;
            }
        }
    }

    float rs0 = 0.f, rs1 = 0.f;
    int lrow0 = w*16 + g, lrow1 = lrow0 + 8;

    for (int kt = 0; kt <= qt; kt++) {
        int cur = kt & 1;
        CP_WAIT0();
        __syncthreads();
        if (kt < qt) {
            const __half* src = ksrc + (size_t)(kt + 1)*64*HS;
            #pragma unroll
            for (int s = 0; s < 4; s++) {
                int ff = tid + s*128;
                int row = ff >> 3, c8 = ff & 7;
                cp_async16(&RawK[cur ^ 1][row][c8*8], src + (size_t)row*HS + c8*8);
            }
            CP_COMMIT();
        }

        #pragma unroll
        for (int nf = 0; nf < 8; nf++) {
            float acc[4] = {0.f, 0.f, 0.f, 0.f};
            int n = nf*8 + g;
            #pragma unroll
            for (int ks = 0; ks < 4; ks++) {
                uint32_t b0 = *(const uint32_t*)&RawK[cur][n][ks*16 + tig*2];
                uint32_t b1 = *(const uint32_t*)&RawK[cur][n][ks*16 + 8 + tig*2];
                mma_f16(acc, qh[ks], b0, b1);
            }
            int lcol = nf*8 + tig*2;
            float e00 = exp2f(acc[0]*SC);
            float e01 = exp2f(acc[1]*SC);
            float e10 = exp2f(acc[2]*SC);
            float e11 = exp2f(acc[3]*SC);
            if (kt == qt) {
                if (lcol     > lrow0) e00 = 0.f;
                if (lcol + 1 > lrow0) e01 = 0.f;
                if (lcol     > lrow1) e10 = 0.f;
                if (lcol + 1 > lrow1) e11 = 0.f;
            }
            rs0 += e00 + e01; rs1 += e10 + e11;
            size_t base = ((size_t)bh*TT + qt*64 + lrow0)*TT + kt*64 + lcol;
            *(__half2*)&g_probs[base]        = __floats2half2_rn(e00, e01);
            *(__half2*)&g_probs[base + 8*TT] = __floats2half2_rn(e10, e11);
        }
    }

    #pragma unroll
    for (int o = 1; o < 4; o <<= 1) {
        rs0 += __shfl_xor_sync(0xffffffffu, rs0, o);
        rs1 += __shfl_xor_sync(0xffffffffu, rs1, o);
    }
    if (tig == 0) {
        int r = bh*TT + qt*64 + lrow0;
        float i0 = 1.0f / rs0, i1 = 1.0f / rs1;
        g_rowinv[r]     = i0;
        g_rowinv[r + 8] = i1;
        sinv[lrow0]     = i0;
        sinv[lrow1]     = i1;
    }
    __syncthreads();

    int nk = (qt + 1) * 64;
    const __half* strip = g_probs + ((size_t)bh*TT + qt*64)*TT;
    for (int k = tid; k < nk; k += 128) {
        float s0 = 0.f, s1 = 0.f, s2 = 0.f, s3 = 0.f;
        #pragma unroll
        for (int i = 0; i < 64; i += 4) {
            s0 += __half2float(strip[(size_t)(i    ) * TT + k]) * sinv[i    ];
            s1 += __half2float(strip[(size_t)(i + 1) * TT + k]) * sinv[i + 1];
            s2 += __half2float(strip[(size_t)(i + 2) * TT + k]) * sinv[i + 2];
            s3 += __half2float(strip[(size_t)(i + 3) * TT + k]) * sinv[i + 3];
        }
        atomicAdd(&g_colsum[bh*TT + k], (s0 + s1) + (s2 + s3));
    }
}

// ---------------------------------------------------------------------------
// eff precompute
// ---------------------------------------------------------------------------
__global__ __launch_bounds__(256)
void eff_kernel(const float* __restrict__ refst,
                const float* __restrict__ threshold,
                const float* __restrict__ steepness,
                const float* __restrict__ ref_strength,
                const float* __restrict__ cross_w) {
    int bh = blockIdx.y;
    int b = bh >> 4, h = bh & 15;
    float thr = fabsf(threshold[h]) * 0.1f;
    float st  = softplusf_(steepness[h]);
    float rsp = softplusf_(ref_strength[h]) * (1.0f/1024.0f);
    float cw  = sigmoidf_(cross_w[h]);
    float stl2 = st * LOG2E;
    int k = blockIdx.x * 256 + threadIdx.x;
    float c = g_colsum[bh*TT + k];
    float f = refst[b*TT + k];
    g_effc[bh*TT + k] = stl2 * (thr + rsp * c + cw * f);
}

// ---------------------------------------------------------------------------
// lif modulate + renormalize (fp16 probs in/out, normalization folded)
// ---------------------------------------------------------------------------
__global__ __launch_bounds__(128)
void lifmod_kernel(const float* __restrict__ leak,
                   const float* __restrict__ steepness) {
    int r = blockIdx.x;
    int bh = r >> 10;
    int q = r & (TT - 1);
    int nk = ((q >> 6) + 1) * 64;
    int h = bh & 15;
    int tid = threadIdx.x;
    int wid = tid >> 5, lane = tid & 31;
    float lk  = sigmoidf_(leak[h]);
    float dl  = 1.0f - lk;
    float st  = softplusf_(steepness[h]);
    float rinv = g_rowinv[r];
    float nstl2r = -st * LOG2E * rinv;
    size_t base = (size_t)r * TT;
    const float* effc = g_effc + bh*TT;
    float mv[8];
    float sum = 0.0f;
    #pragma unroll
    for (int i = 0; i < 2; i++) {
        int k = i * 512 + tid * 4;
        if (k < nk) {
            __half2 h01 = *(const __half2*)&g_probs[base + k];
            __half2 h23 = *(const __half2*)&g_probs[base + k + 2];
            float2 f01 = __half22float2(h01);
            float2 f23 = __half22float2(h23);
            float4 c4 = *(const float4*)&effc[k];
            float pp[4] = {f01.x, f01.y, f23.x, f23.y};
            float cc[4] = {c4.x, c4.y, c4.z, c4.w};
            #pragma unroll
            for (int j = 0; j < 4; j++) {
                float z = fmaf(nstl2r, pp[j], cc[j]);
                float fire = __frcp_rn(1.0f + exp2f(z));
                float m = pp[j] * fmaf(dl, fire, lk);
                mv[i*4 + j] = m;
                sum += m;
            }
        } else {
            mv[i*4] = mv[i*4+1] = mv[i*4+2] = mv[i*4+3] = 0.0f;
        }
    }
    #pragma unroll
    for (int o = 16; o > 0; o >>= 1) sum += __shfl_xor_sync(0xffffffffu, sum, o);
    __shared__ float red[4];
    if (lane == 0) red[wid] = sum;
    __syncthreads();
    float tot = red[0] + red[1] + red[2] + red[3];
    float scale = rinv / (fmaf(rinv, tot, 1e-8f));
    #pragma unroll
    for (int i = 0; i < 2; i++) {
        int k = i * 512 + tid * 4;
        if (k < nk) {
            *(__half2*)&g_probs[base + k]     = __floats2half2_rn(mv[i*4]*scale,   mv[i*4+1]*scale);
            *(__half2*)&g_probs[base + k + 2] = __floats2half2_rn(mv[i*4+2]*scale, mv[i*4+3]*scale);
        }
    }
}

// ---------------------------------------------------------------------------
// y_pre = mod @ V. fp16 HMMA, fp16 ypre output. Fused refractory reduce.
// ---------------------------------------------------------------------------
__global__ __launch_bounds__(128, 3)
void modv_kernel(float* __restrict__ refout) {
    int qt = (int)gridDim.x - 1 - (int)blockIdx.x;
    int bh = blockIdx.y;
    int b = bh >> 4;
    __shared__ __half RawM[2][64][72];
    __shared__ __half RawVT[2][64][72];
    int tid = threadIdx.x;
    int w = tid >> 5, lane = tid & 31;
    int g = lane >> 2, tig = lane & 3;

    const __half* msrc_base = g_probs + ((size_t)bh*TT + qt*64)*TT;
    const __half* vtsrc     = g_vht + (size_t)bh*HS*TT;

    float acc[8][4];
    #pragma unroll
    for (int nf = 0; nf < 8; nf++)
        #pragma unroll
        for (int i = 0; i < 4; i++) acc[nf][i] = 0.0f;

    {
        #pragma unroll
        for (int s = 0; s < 4; s++) {
            int ff = tid + s*128;
            int row = ff >> 3, c8 = ff & 7;
            cp_async16(&RawM[0][row][c8*8],  msrc_base + (size_t)row*TT + c8*8);
            cp_async16(&RawVT[0][row][c8*8], vtsrc + (size_t)row*TT + c8*8);
        }
        CP_COMMIT();
    }

    for (int kt = 0; kt <= qt; kt++) {
        int cur = kt & 1;
        CP_WAIT0();
        __syncthreads();
        if (kt < qt) {
            const __half* ms = msrc_base + (kt + 1)*64;
            const __half* vs = vtsrc + (kt + 1)*64;
            #pragma unroll
            for (int s = 0; s < 4; s++) {
                int ff = tid + s*128;
                int row = ff >> 3, c8 = ff & 7;
                cp_async16(&RawM[cur ^ 1][row][c8*8],  ms + (size_t)row*TT + c8*8);
                cp_async16(&RawVT[cur ^ 1][row][c8*8], vs + (size_t)row*TT + c8*8);
            }
            CP_COMMIT();
        }

        if (tid < 64) {
            float s = 0.0f;
            #pragma unroll 8
            for (int i = 0; i < 64; i++) s += __half2float(RawM[cur][i][tid]);
            atomicAdd(&refout[b*TT + kt*64 + tid], s * (1.0f / 16384.0f));
        }

        #pragma unroll
        for (int ks = 0; ks < 4; ks++) {
            uint32_t ah[4];
            int r0 = w*16 + g;
            int c0 = ks*16 + tig*2;
            ah[0] = *(const uint32_t*)&RawM[cur][r0    ][c0    ];
            ah[1] = *(const uint32_t*)&RawM[cur][r0 + 8][c0    ];
            ah[2] = *(const uint32_t*)&RawM[cur][r0    ][c0 + 8];
            ah[3] = *(const uint32_t*)&RawM[cur][r0 + 8][c0 + 8];
            #pragma unroll
            for (int nf = 0; nf < 8; nf++) {
                int n = nf*8 + g;
                uint32_t b0 = *(const uint32_t*)&RawVT[cur][n][c0    ];
                uint32_t b1 = *(const uint32_t*)&RawVT[cur][n][c0 + 8];
                mma_f16(acc[nf], ah, b0, b1);
            }
        }
    }

    #pragma unroll
    for (int nf = 0; nf < 8; nf++) {
        int row = qt*64 + w*16 + g;
        int col = nf*8 + tig*2;
        int h = bh & 15;
        __half* dst = g_ypreh + (size_t)(b*TT + row)*CC + h*HS + col;
        *(__half2*)dst          = __floats2half2_rn(acc[nf][0], acc[nf][1]);
        *(__half2*)(dst + 8*CC) = __floats2half2_rn(acc[nf][2], acc[nf][3]);
    }
}

// ---------------------------------------------------------------------------
extern "C" void kernel_launch(void* const* d_in, const int* in_sizes, int n_in,
                              void* d_out, int out_size) {
    const float* x      = (const float*)d_in[0];
    const float* refst  = (const float*)d_in[1];
    const float* W_attn = (const float*)d_in[2];
    const float* b_attn = (const float*)d_in[3];
    const float* W_proj = (const float*)d_in[4];
    const float* b_proj = (const float*)d_in[5];
    const float* thr    = (const float*)d_in[6];
    const float* leak   = (const float*)d_in[7];
    const float* steep  = (const float*)d_in[8];
    const float* refstr = (const float*)d_in[9];
    const float* crossw = (const float*)d_in[10];

    float* y_out   = (float*)d_out;
    float* ref_out = (float*)d_out + (size_t)BB*TT*CC;

    float*  qkv   = nullptr;  cudaGetSymbolAddress((void**)&qkv,   g_qkv);
    __half* xh    = nullptr;  cudaGetSymbolAddress((void**)&xh,    g_xh);
    __half* wat   = nullptr;  cudaGetSymbolAddress((void**)&wat,   g_wat);
    __half* wpt   = nullptr;  cudaGetSymbolAddress((void**)&wpt,   g_wpt);
    __half* ypreh = nullptr;  cudaGetSymbolAddress((void**)&ypreh, g_ypreh);

    init_kernel<<<(BHT*TT + 255)/256, 256>>>(ref_out);
    xconvert_kernel<<<(BB*TT*CC)/(256*8), 256>>>(x);
    wtrans_kernel<<<dim3(C3/64, CC/64), 256>>>(W_attn, wat, C3);
    wtrans_kernel<<<dim3(CC/64, CC/64), 256>>>(W_proj, wpt, CC);
    gemm_f16_kernel<<<dim3(C3/128, (BB*TT)/128), 256>>>(xh, wat, b_attn, qkv, BB*TT, C3, CC);
    kvconvert_kernel<<<BHT, 256>>>();
    scores_exp_kernel<<<dim3(TT/64, BHT), 128>>>();
    eff_kernel<<<dim3(TT/256, BHT), 256>>>(refst, thr, steep, refstr, crossw);
    lifmod_kernel<<<NROWS, 128>>>(leak, steep);
    modv_kernel<<<dim3(TT/64, BHT), 128>>>(ref_out);
    gemm_f16_kernel<<<dim3(CC/128, (BB*TT)/128), 256>>>(ypreh, wpt, b_proj, y_out, BB*TT, CC, CC);
}